// round 4
// baseline (speedup 1.0000x reference)
#include <cuda_runtime.h>
#include <math.h>

// ---------------- problem constants ----------------
#define Dm      1024
#define Hh      16
#define DHd     64
#define Ff      4096
#define Ee      8
#define TOPK    2
#define Bbat    2
#define Sseq    2048
#define Ntok    4096
#define NKCAP   16384

// GEMM tiling
#define AP 36
#define BP 136
#define GEMM_ASZ (128 * AP)
#define GEMM_BSZ (32 * BP)
#define GEMM_STG (GEMM_ASZ + GEMM_BSZ)
#define GEMM_SMEM (2 * GEMM_STG * 4)

// flash tiling
#define QT   128
#define KC   64
#define KSP  68
#define VSP  72
#define PSP  68
#define FL_KSZ (KC * KSP)
#define FL_VSZ (KC * VSP)
#define FL_STG (FL_KSZ + FL_VSZ)
#define FLASH_SMEM ((2 * FL_STG + QT * PSP) * 4)

// ---------------- device scratch ----------------
__device__ float g_Q [Ntok * Dm];
__device__ float g_K [Ntok * Dm];
__device__ float g_V [Ntok * Dm];
__device__ float g_AT[Ntok * Dm];
__device__ float g_PR[Ntok * Dm];
__device__ float g_X1[Ntok * Dm];
__device__ float g_X2[Ntok * Dm];

__device__ float g_XG[(size_t)NKCAP * Dm];
__device__ float g_HB[(size_t)NKCAP * Ff];
__device__ float g_YG[(size_t)NKCAP * Dm];
__device__ float g_MO[Ntok * Dm];

__device__ int   g_tok_e[Ntok * TOPK];
__device__ float g_tok_g[Ntok * TOPK];
__device__ int   g_cnt[Ee];
__device__ int   g_cur[Ee];
__device__ int   g_off[Ee + 1];
__device__ int   g_row_tok[NKCAP];
__device__ float g_row_gate[NKCAP];
__device__ float g_auxp[Ntok * Ee];
__device__ int   g_auxi[Ntok * TOPK];

// ---------------- helpers ----------------
__device__ __forceinline__ void mma_tf32(float* c, const unsigned* a, const unsigned* b) {
    asm volatile(
        "mma.sync.aligned.m16n8k8.row.col.f32.tf32.tf32.f32 "
        "{%0,%1,%2,%3},{%4,%5,%6,%7},{%8,%9},{%0,%1,%2,%3};\n"
        : "+f"(c[0]), "+f"(c[1]), "+f"(c[2]), "+f"(c[3])
        : "r"(a[0]), "r"(a[1]), "r"(a[2]), "r"(a[3]), "r"(b[0]), "r"(b[1]));
}

__device__ __forceinline__ void cp16(float* smem, const float* gmem, bool pred) {
    unsigned saddr = (unsigned)__cvta_generic_to_shared(smem);
    int sz = pred ? 16 : 0;
    asm volatile("cp.async.ca.shared.global [%0], [%1], 16, %2;\n"
                 :: "r"(saddr), "l"(gmem), "r"(sz));
}
__device__ __forceinline__ void cp_commit() {
    asm volatile("cp.async.commit_group;\n");
}
__device__ __forceinline__ void cp_wait1() {
    asm volatile("cp.async.wait_group 1;\n" ::: "memory");
}

// ---------------- tensor-core GEMM: 128x128x32, 2-stage cp.async ----------------
__device__ __forceinline__ void gemm_stage(
    float* As, float* Bs,
    const float* __restrict__ A, int lda,
    const float* __restrict__ Bg, int ldb,
    int bm, int bn, int k0, int M, int tid)
{
#pragma unroll
    for (int i = 0; i < 4; i++) {
        int idx = tid + i * 256;
        int r = idx >> 3, c = (idx & 7) << 2;
        bool p = (bm + r) < M;
        const float* src = A + (size_t)(p ? (bm + r) : 0) * lda + k0 + c;
        cp16(&As[r * AP + c], src, p);
    }
#pragma unroll
    for (int i = 0; i < 4; i++) {
        int idx = tid + i * 256;
        int r = idx >> 5, c = (idx & 31) << 2;
        cp16(&Bs[r * BP + c], Bg + (size_t)(k0 + r) * ldb + bn + c, true);
    }
}

__device__ __forceinline__ void mma_gemm_tile(
    const float* __restrict__ A, int lda,
    const float* __restrict__ Bg, int ldb,
    const float* __restrict__ bias,
    float* __restrict__ C, int ldc,
    int M, int Kd, int bm, int bn, int relu)
{
    extern __shared__ float smp[];
    float* stage[2] = { smp, smp + GEMM_STG };

    const int tid  = threadIdx.x;
    const int lane = tid & 31;
    const int wid  = tid >> 5;
    const int wm = (wid >> 2) * 64;
    const int wn = (wid & 3) * 32;
    const int g  = lane >> 2;
    const int tg = lane & 3;

    float acc[4][4][4];
#pragma unroll
    for (int i = 0; i < 4; i++)
#pragma unroll
        for (int j = 0; j < 4; j++)
#pragma unroll
            for (int q = 0; q < 4; q++) acc[i][j][q] = 0.f;

    const int ktiles = Kd / 32;

    gemm_stage(stage[0], stage[0] + GEMM_ASZ, A, lda, Bg, ldb, bm, bn, 0, M, tid);
    cp_commit();
    gemm_stage(stage[1], stage[1] + GEMM_ASZ, A, lda, Bg, ldb, bm, bn, 32, M, tid);
    cp_commit();
    cp_wait1();
    __syncthreads();

    for (int t = 0; t < ktiles; t++) {
        const unsigned* As = (const unsigned*)stage[t & 1];
        const unsigned* Bs = (const unsigned*)(stage[t & 1] + GEMM_ASZ);

#pragma unroll
        for (int ks = 0; ks < 4; ks++) {
            const int k = ks * 8;
            unsigned af[4][4], bf[4][2];
#pragma unroll
            for (int mt = 0; mt < 4; mt++) {
                int mb = wm + mt * 16;
                af[mt][0] = As[(mb + g)     * AP + k + tg];
                af[mt][1] = As[(mb + g + 8) * AP + k + tg];
                af[mt][2] = As[(mb + g)     * AP + k + tg + 4];
                af[mt][3] = As[(mb + g + 8) * AP + k + tg + 4];
            }
#pragma unroll
            for (int nt = 0; nt < 4; nt++) {
                int nb = wn + nt * 8;
                bf[nt][0] = Bs[(k + tg)     * BP + nb + g];
                bf[nt][1] = Bs[(k + tg + 4) * BP + nb + g];
            }
#pragma unroll
            for (int mt = 0; mt < 4; mt++)
#pragma unroll
                for (int nt = 0; nt < 4; nt++)
                    mma_tf32(acc[mt][nt], af[mt], bf[nt]);
        }
        __syncthreads();
        if (t + 2 < ktiles) {
            float* dst = stage[t & 1];
            gemm_stage(dst, dst + GEMM_ASZ, A, lda, Bg, ldb, bm, bn, (t + 2) * 32, M, tid);
        }
        cp_commit();
        cp_wait1();
        __syncthreads();
    }

#pragma unroll
    for (int mt = 0; mt < 4; mt++) {
#pragma unroll
        for (int nt = 0; nt < 4; nt++) {
            int row0 = bm + wm + mt * 16 + g;
            int col  = bn + wn + nt * 8 + tg * 2;
            float b0 = bias ? bias[col]     : 0.f;
            float b1 = bias ? bias[col + 1] : 0.f;
            float v0 = acc[mt][nt][0] + b0;
            float v1 = acc[mt][nt][1] + b1;
            float v2 = acc[mt][nt][2] + b0;
            float v3 = acc[mt][nt][3] + b1;
            if (relu) {
                v0 = fmaxf(v0, 0.f); v1 = fmaxf(v1, 0.f);
                v2 = fmaxf(v2, 0.f); v3 = fmaxf(v3, 0.f);
            }
            if (row0 < M)     *(float2*)(C + (size_t)row0 * ldc + col)       = make_float2(v0, v1);
            if (row0 + 8 < M) *(float2*)(C + (size_t)(row0 + 8) * ldc + col) = make_float2(v2, v3);
        }
    }
}

__global__ void __launch_bounds__(256) k_gemm128(
    const float* __restrict__ A, int lda, const float* __restrict__ B, int ldb,
    const float* __restrict__ bias, float* __restrict__ C, int ldc, int M, int Kd, int relu)
{
    mma_gemm_tile(A, lda, B, ldb, bias, C, ldc, M, Kd,
                  blockIdx.x * 128, blockIdx.y * 128, relu);
}

__global__ void __launch_bounds__(256) k_moe_gemm_mma(
    const float* __restrict__ Abase, const float* __restrict__ Wbase,
    const float* __restrict__ bbase, float* __restrict__ Cbase, int Kd, int Nn, int relu)
{
    int e = blockIdx.z;
    int cnt = g_cnt[e];
    int bm = blockIdx.x * 128;
    if (bm >= cnt) return;
    int off = g_off[e];
    mma_gemm_tile(Abase + (size_t)off * Kd, Kd,
                  Wbase + (size_t)e * Kd * Nn, Nn,
                  bbase + (size_t)e * Nn,
                  Cbase + (size_t)off * Nn, Nn,
                  cnt, Kd, bm, blockIdx.y * 128, relu);
}

// ---------------- flash attention (cp.async 2-stage K/V pipeline) ----------------
__device__ __forceinline__ void flash_stage(
    float* Ks, float* Vs, const float* __restrict__ Kp,
    const float* __restrict__ Vp, int kc0, int tid)
{
#pragma unroll
    for (int i = 0; i < 4; i++) {
        int idx = tid + i * 256;
        int r = idx >> 4, c = (idx & 15) << 2;
        cp16(&Ks[r * KSP + c], Kp + (size_t)(kc0 + r) * Dm + c, true);
        cp16(&Vs[r * VSP + c], Vp + (size_t)(kc0 + r) * Dm + c, true);
    }
}

__global__ void __launch_bounds__(256) k_flash(
    const float* __restrict__ Qg, const float* __restrict__ Kg,
    const float* __restrict__ Vg, float* __restrict__ AT)
{
    extern __shared__ float sm[];
    float* kstage[2] = { sm, sm + FL_STG };
    unsigned* Ps = (unsigned*)(sm + 2 * FL_STG);

    const int bh = blockIdx.y;
    const int b = bh >> 4, h = bh & 15;
    const int q0 = blockIdx.x * QT;
    const int tid = threadIdx.x;
    const int lane = tid & 31;
    const int wid = tid >> 5;
    const int g = lane >> 2;
    const int tg = lane & 3;
    const int wrow = wid * 16;

    const float* Qp = Qg + (size_t)b * Sseq * Dm + h * DHd;
    const float* Kp = Kg + (size_t)b * Sseq * Dm + h * DHd;
    const float* Vp = Vg + (size_t)b * Sseq * Dm + h * DHd;

    unsigned qf[8][4];
#pragma unroll
    for (int kt = 0; kt < 8; kt++) {
        int k = kt * 8;
        qf[kt][0] = __float_as_uint(Qp[(size_t)(q0 + wrow + g)     * Dm + k + tg]);
        qf[kt][1] = __float_as_uint(Qp[(size_t)(q0 + wrow + g + 8) * Dm + k + tg]);
        qf[kt][2] = __float_as_uint(Qp[(size_t)(q0 + wrow + g)     * Dm + k + tg + 4]);
        qf[kt][3] = __float_as_uint(Qp[(size_t)(q0 + wrow + g + 8) * Dm + k + tg + 4]);
    }

    float oacc[8][4];
#pragma unroll
    for (int i = 0; i < 8; i++)
#pragma unroll
        for (int j = 0; j < 4; j++) oacc[i][j] = 0.f;
    float m0 = -1e30f, m1 = -1e30f, l0 = 0.f, l1 = 0.f;

    flash_stage(kstage[0], kstage[0] + FL_KSZ, Kp, Vp, 0, tid);
    cp_commit();
    flash_stage(kstage[1], kstage[1] + FL_KSZ, Kp, Vp, KC, tid);
    cp_commit();
    cp_wait1();
    __syncthreads();

    const int nchunks = Sseq / KC;
    for (int c = 0; c < nchunks; c++) {
        const unsigned* Ks = (const unsigned*)kstage[c & 1];
        const unsigned* Vs = (const unsigned*)(kstage[c & 1] + FL_KSZ);

        // ---- S = Q K^T ----
        float sacc[8][4];
#pragma unroll
        for (int i = 0; i < 8; i++)
#pragma unroll
            for (int j = 0; j < 4; j++) sacc[i][j] = 0.f;
#pragma unroll
        for (int kt = 0; kt < 8; kt++) {
            int k = kt * 8;
            unsigned bf[8][2];
#pragma unroll
            for (int nt = 0; nt < 8; nt++) {
                bf[nt][0] = Ks[(nt * 8 + g) * KSP + k + tg];
                bf[nt][1] = Ks[(nt * 8 + g) * KSP + k + tg + 4];
            }
#pragma unroll
            for (int nt = 0; nt < 8; nt++)
                mma_tf32(sacc[nt], qf[kt], bf[nt]);
        }

        // ---- online softmax ----
        float mx0 = -1e30f, mx1 = -1e30f;
#pragma unroll
        for (int nt = 0; nt < 8; nt++) {
            sacc[nt][0] *= 0.125f; sacc[nt][1] *= 0.125f;
            sacc[nt][2] *= 0.125f; sacc[nt][3] *= 0.125f;
            mx0 = fmaxf(mx0, fmaxf(sacc[nt][0], sacc[nt][1]));
            mx1 = fmaxf(mx1, fmaxf(sacc[nt][2], sacc[nt][3]));
        }
        mx0 = fmaxf(mx0, __shfl_xor_sync(0xffffffff, mx0, 1));
        mx0 = fmaxf(mx0, __shfl_xor_sync(0xffffffff, mx0, 2));
        mx1 = fmaxf(mx1, __shfl_xor_sync(0xffffffff, mx1, 1));
        mx1 = fmaxf(mx1, __shfl_xor_sync(0xffffffff, mx1, 2));
        float nm0 = fmaxf(m0, mx0), nm1 = fmaxf(m1, mx1);
        float sc0 = __expf(m0 - nm0), sc1 = __expf(m1 - nm1);
        float ps0 = 0.f, ps1 = 0.f;
#pragma unroll
        for (int nt = 0; nt < 8; nt++) {
            float p00 = __expf(sacc[nt][0] - nm0);
            float p01 = __expf(sacc[nt][1] - nm0);
            float p10 = __expf(sacc[nt][2] - nm1);
            float p11 = __expf(sacc[nt][3] - nm1);
            ps0 += p00 + p01; ps1 += p10 + p11;
            int col = nt * 8 + tg * 2;
            *(uint2*)&Ps[(wrow + g)     * PSP + col] =
                make_uint2(__float_as_uint(p00), __float_as_uint(p01));
            *(uint2*)&Ps[(wrow + g + 8) * PSP + col] =
                make_uint2(__float_as_uint(p10), __float_as_uint(p11));
        }
        ps0 += __shfl_xor_sync(0xffffffff, ps0, 1);
        ps0 += __shfl_xor_sync(0xffffffff, ps0, 2);
        ps1 += __shfl_xor_sync(0xffffffff, ps1, 1);
        ps1 += __shfl_xor_sync(0xffffffff, ps1, 2);
        l0 = l0 * sc0 + ps0; l1 = l1 * sc1 + ps1;
        m0 = nm0; m1 = nm1;
#pragma unroll
        for (int nt = 0; nt < 8; nt++) {
            oacc[nt][0] *= sc0; oacc[nt][1] *= sc0;
            oacc[nt][2] *= sc1; oacc[nt][3] *= sc1;
        }
        __syncwarp();

        // ---- O += P V ----
#pragma unroll
        for (int kt = 0; kt < 8; kt++) {
            int k = kt * 8;
            unsigned af[4];
            af[0] = Ps[(wrow + g)     * PSP + k + tg];
            af[1] = Ps[(wrow + g + 8) * PSP + k + tg];
            af[2] = Ps[(wrow + g)     * PSP + k + tg + 4];
            af[3] = Ps[(wrow + g + 8) * PSP + k + tg + 4];
            unsigned bf[8][2];
#pragma unroll
            for (int nt = 0; nt < 8; nt++) {
                bf[nt][0] = Vs[(k + tg)     * VSP + nt * 8 + g];
                bf[nt][1] = Vs[(k + tg + 4) * VSP + nt * 8 + g];
            }
#pragma unroll
            for (int nt = 0; nt < 8; nt++)
                mma_tf32(oacc[nt], af, bf[nt]);
        }
        __syncthreads();
        if (c + 2 < nchunks) {
            float* dst = kstage[c & 1];
            flash_stage(dst, dst + FL_KSZ, Kp, Vp, (c + 2) * KC, tid);
        }
        cp_commit();
        cp_wait1();
        __syncthreads();
    }

    float inv0 = 1.f / l0, inv1 = 1.f / l1;
    float* Op = AT + (size_t)b * Sseq * Dm + h * DHd;
#pragma unroll
    for (int nt = 0; nt < 8; nt++) {
        int col = nt * 8 + tg * 2;
        *(float2*)(Op + (size_t)(q0 + wrow + g) * Dm + col) =
            make_float2(oacc[nt][0] * inv0, oacc[nt][1] * inv0);
        *(float2*)(Op + (size_t)(q0 + wrow + g + 8) * Dm + col) =
            make_float2(oacc[nt][2] * inv1, oacc[nt][3] * inv1);
    }
}

// ---------------- layernorm(residual) ----------------
__global__ void k_ln_res(const float* __restrict__ X, const float* __restrict__ R,
                         const float* __restrict__ gw, const float* __restrict__ bw,
                         float* __restrict__ O)
{
    int t = blockIdx.x, tid = threadIdx.x;
    const float* xp = X + (size_t)t * Dm;
    const float* rp = R + (size_t)t * Dm;
    float v[4]; float s = 0.f;
#pragma unroll
    for (int i = 0; i < 4; i++) { int d = tid + i * 256; v[i] = xp[d] + rp[d]; s += v[i]; }
    __shared__ float red[256];
    red[tid] = s; __syncthreads();
    for (int st = 128; st > 0; st >>= 1) {
        if (tid < st) red[tid] += red[tid + st];
        __syncthreads();
    }
    float mean = red[0] * (1.f / Dm);
    __syncthreads();
    float s2 = 0.f;
#pragma unroll
    for (int i = 0; i < 4; i++) { float dd = v[i] - mean; s2 += dd * dd; }
    red[tid] = s2; __syncthreads();
    for (int st = 128; st > 0; st >>= 1) {
        if (tid < st) red[tid] += red[tid + st];
        __syncthreads();
    }
    float rstd = rsqrtf(red[0] * (1.f / Dm) + 1e-5f);
    float* op = O + (size_t)t * Dm;
#pragma unroll
    for (int i = 0; i < 4; i++) {
        int d = tid + i * 256;
        op[d] = (v[i] - mean) * rstd * gw[d] + bw[d];
    }
}

// ---------------- MoE routing / dispatch ----------------
__global__ void k_moe_init()
{
    int tid = threadIdx.x;
    if (tid < Ee) { g_cnt[tid] = 0; g_cur[tid] = 0; }
    for (int i = tid; i < NKCAP; i += 256) g_row_tok[i] = -1;
}

__global__ void k_router(const float* __restrict__ X,
                         const float* __restrict__ rw,
                         const float* __restrict__ rb,
                         int mode)
{
    int t = blockIdx.x, tid = threadIdx.x;
    const float* xp = X + (size_t)t * Dm;
    float loc[Ee];
#pragma unroll
    for (int e = 0; e < Ee; e++) loc[e] = 0.f;
    for (int d = tid; d < Dm; d += 256) {
        float xv = xp[d];
#pragma unroll
        for (int e = 0; e < Ee; e++) loc[e] += xv * rw[d * Ee + e];
    }
    __shared__ float red[256 * Ee];
#pragma unroll
    for (int e = 0; e < Ee; e++) red[tid * Ee + e] = loc[e];
    __syncthreads();
    for (int st = 128; st > 0; st >>= 1) {
        if (tid < st)
#pragma unroll
            for (int e = 0; e < Ee; e++)
                red[tid * Ee + e] += red[(tid + st) * Ee + e];
        __syncthreads();
    }
    if (tid == 0) {
        float lg[Ee], mx = -1e30f;
#pragma unroll
        for (int e = 0; e < Ee; e++) { lg[e] = red[e] + rb[e]; mx = fmaxf(mx, lg[e]); }
        float sm = 0.f;
#pragma unroll
        for (int e = 0; e < Ee; e++) { lg[e] = expf(lg[e] - mx); sm += lg[e]; }
        float inv = 1.f / sm;
#pragma unroll
        for (int e = 0; e < Ee; e++) lg[e] *= inv;
        int e0 = 0;
#pragma unroll
        for (int e = 1; e < Ee; e++) if (lg[e] > lg[e0]) e0 = e;
        int e1 = -1;
#pragma unroll
        for (int e = 0; e < Ee; e++)
            if (e != e0 && (e1 < 0 || lg[e] > lg[e1])) e1 = e;
        if (mode == 0) {
            float g0 = lg[e0], g1 = lg[e1], gs = g0 + g1;
            g_tok_e[t * 2] = e0;  g_tok_e[t * 2 + 1] = e1;
            g_tok_g[t * 2] = g0 / gs; g_tok_g[t * 2 + 1] = g1 / gs;
            atomicAdd(&g_cnt[e0], 1); atomicAdd(&g_cnt[e1], 1);
        } else {
#pragma unroll
            for (int e = 0; e < Ee; e++) g_auxp[t * Ee + e] = lg[e];
            g_auxi[t * 2] = e0; g_auxi[t * 2 + 1] = e1;
        }
    }
}

__global__ void k_offsets()
{
    if (threadIdx.x == 0) {
        int acc = 0;
        for (int e = 0; e < Ee; e++) {
            g_off[e] = acc;
            acc += ((g_cnt[e] + 127) >> 7) << 7;
        }
        g_off[Ee] = acc;
    }
}

__global__ void k_gather(const float* __restrict__ X)
{
    int t = blockIdx.x, tid = threadIdx.x;
    __shared__ int spos[TOPK];
    if (tid == 0) {
#pragma unroll
        for (int k = 0; k < TOPK; k++) {
            int e = g_tok_e[t * 2 + k];
            int p = g_off[e] + atomicAdd(&g_cur[e], 1);
            spos[k] = p;
            g_row_tok[p] = t;
            g_row_gate[p] = g_tok_g[t * 2 + k];
        }
    }
    __syncthreads();
    const float4* src = reinterpret_cast<const float4*>(X + (size_t)t * Dm);
#pragma unroll
    for (int k = 0; k < TOPK; k++) {
        float4* dst = reinterpret_cast<float4*>(g_XG + (size_t)spos[k] * Dm);
        dst[tid] = src[tid];
    }
}

__global__ void k_zero_mo()
{
    int t = blockIdx.x, tid = threadIdx.x;
    float4 z = make_float4(0.f, 0.f, 0.f, 0.f);
    reinterpret_cast<float4*>(g_MO + (size_t)t * Dm)[tid] = z;
}

__global__ void k_scatter()
{
    int p = blockIdx.x;
    int t = g_row_tok[p];
    if (t < 0) return;
    float gt = g_row_gate[p];
    int tid = threadIdx.x;
    for (int d = tid; d < Dm; d += 256)
        atomicAdd(&g_MO[(size_t)t * Dm + d], gt * g_YG[(size_t)p * Dm + d]);
}

__global__ void k_aux_final(float* __restrict__ out)
{
    int tid = threadIdx.x;
    float imp[Ee];
#pragma unroll
    for (int e = 0; e < Ee; e++) imp[e] = 0.f;
    for (int t = tid; t < Ntok; t += 256)
#pragma unroll
        for (int e = 0; e < Ee; e++) imp[e] += g_auxp[t * Ee + e];
    float ld[Ee];
#pragma unroll
    for (int e = 0; e < Ee; e++) ld[e] = 0.f;
    for (int i = tid; i < Ntok * TOPK; i += 256) ld[g_auxi[i]] += 1.f;

    __shared__ float red[256 * Ee];
    __shared__ float simp[Ee];
#pragma unroll
    for (int e = 0; e < Ee; e++) red[tid * Ee + e] = imp[e];
    __syncthreads();
    for (int st = 128; st > 0; st >>= 1) {
        if (tid < st)
#pragma unroll
            for (int e = 0; e < Ee; e++)
                red[tid * Ee + e] += red[(tid + st) * Ee + e];
        __syncthreads();
    }
    if (tid == 0)
#pragma unroll
        for (int e = 0; e < Ee; e++) simp[e] = red[e];
    __syncthreads();
#pragma unroll
    for (int e = 0; e < Ee; e++) red[tid * Ee + e] = ld[e];
    __syncthreads();
    for (int st = 128; st > 0; st >>= 1) {
        if (tid < st)
#pragma unroll
            for (int e = 0; e < Ee; e++)
                red[tid * Ee + e] += red[(tid + st) * Ee + e];
        __syncthreads();
    }
    if (tid == 0) {
        float aux = 0.f;
#pragma unroll
        for (int e = 0; e < Ee; e++)
            aux += (simp[e] / (float)Ntok) * (red[e] / (float)(Ntok * TOPK));
        out[0] = (float)Ee * aux;
    }
}

// ---------------- host orchestration ----------------
extern "C" void kernel_launch(void* const* d_in, const int* in_sizes, int n_in,
                              void* d_out, int out_size)
{
    (void)in_sizes; (void)n_in;
    const float* x     = (const float*)d_in[0];
    const float* enc   = (const float*)d_in[1];
    const float* sa_wq = (const float*)d_in[2];
    const float* sa_bq = (const float*)d_in[3];
    const float* sa_wk = (const float*)d_in[4];
    const float* sa_bk = (const float*)d_in[5];
    const float* sa_wv = (const float*)d_in[6];
    const float* sa_bv = (const float*)d_in[7];
    const float* sa_wo = (const float*)d_in[8];
    const float* sa_bo = (const float*)d_in[9];
    const float* ca_wq = (const float*)d_in[10];
    const float* ca_bq = (const float*)d_in[11];
    const float* ca_wk = (const float*)d_in[12];
    const float* ca_bk = (const float*)d_in[13];
    const float* ca_wv = (const float*)d_in[14];
    const float* ca_bv = (const float*)d_in[15];
    const float* ca_wo = (const float*)d_in[16];
    const float* ca_bo = (const float*)d_in[17];
    const float* n1_g  = (const float*)d_in[18];
    const float* n1_b  = (const float*)d_in[19];
    const float* n2_g  = (const float*)d_in[20];
    const float* n2_b  = (const float*)d_in[21];
    const float* n3_g  = (const float*)d_in[22];
    const float* n3_b  = (const float*)d_in[23];
    const float* r_w   = (const float*)d_in[24];
    const float* r_b   = (const float*)d_in[25];
    const float* e_w1  = (const float*)d_in[26];
    const float* e_b1  = (const float*)d_in[27];
    const float* e_w2  = (const float*)d_in[28];
    const float* e_b2  = (const float*)d_in[29];

    void *pQ, *pK, *pV, *pAT, *pPR, *pX1, *pX2, *pXG, *pHB, *pYG, *pMO;
    cudaGetSymbolAddress(&pQ,  g_Q);
    cudaGetSymbolAddress(&pK,  g_K);
    cudaGetSymbolAddress(&pV,  g_V);
    cudaGetSymbolAddress(&pAT, g_AT);
    cudaGetSymbolAddress(&pPR, g_PR);
    cudaGetSymbolAddress(&pX1, g_X1);
    cudaGetSymbolAddress(&pX2, g_X2);
    cudaGetSymbolAddress(&pXG, g_XG);
    cudaGetSymbolAddress(&pHB, g_HB);
    cudaGetSymbolAddress(&pYG, g_YG);
    cudaGetSymbolAddress(&pMO, g_MO);
    float* Q  = (float*)pQ;  float* K  = (float*)pK;  float* V  = (float*)pV;
    float* AT = (float*)pAT; float* PR = (float*)pPR;
    float* X1 = (float*)pX1; float* X2 = (float*)pX2;
    float* XG = (float*)pXG; float* HB = (float*)pHB; float* YG = (float*)pYG;
    float* out = (float*)d_out;

    static int smem_set = 0;
    if (!smem_set) {
        cudaFuncSetAttribute(k_flash, cudaFuncAttributeMaxDynamicSharedMemorySize, FLASH_SMEM);
        cudaFuncSetAttribute(k_gemm128, cudaFuncAttributeMaxDynamicSharedMemorySize, GEMM_SMEM);
        cudaFuncSetAttribute(k_moe_gemm_mma, cudaFuncAttributeMaxDynamicSharedMemorySize, GEMM_SMEM);
        smem_set = 1;
    }

    dim3 blk(256);
    dim3 gProj(Ntok / 128, Dm / 128);
    dim3 gFlash(Sseq / QT, Bbat * Hh);

    // ---- self attention ----
    k_gemm128<<<gProj, blk, GEMM_SMEM>>>(x, Dm, sa_wq, Dm, sa_bq, Q, Dm, Ntok, Dm, 0);
    k_gemm128<<<gProj, blk, GEMM_SMEM>>>(x, Dm, sa_wk, Dm, sa_bk, K, Dm, Ntok, Dm, 0);
    k_gemm128<<<gProj, blk, GEMM_SMEM>>>(x, Dm, sa_wv, Dm, sa_bv, V, Dm, Ntok, Dm, 0);
    k_flash<<<gFlash, blk, FLASH_SMEM>>>(Q, K, V, AT);
    k_gemm128<<<gProj, blk, GEMM_SMEM>>>(AT, Dm, sa_wo, Dm, sa_bo, PR, Dm, Ntok, Dm, 0);
    k_ln_res<<<Ntok, blk>>>(x, PR, n1_g, n1_b, X1);

    // ---- cross attention ----
    k_gemm128<<<gProj, blk, GEMM_SMEM>>>(X1,  Dm, ca_wq, Dm, ca_bq, Q, Dm, Ntok, Dm, 0);
    k_gemm128<<<gProj, blk, GEMM_SMEM>>>(enc, Dm, ca_wk, Dm, ca_bk, K, Dm, Ntok, Dm, 0);
    k_gemm128<<<gProj, blk, GEMM_SMEM>>>(enc, Dm, ca_wv, Dm, ca_bv, V, Dm, Ntok, Dm, 0);
    k_flash<<<gFlash, blk, FLASH_SMEM>>>(Q, K, V, AT);
    k_gemm128<<<gProj, blk, GEMM_SMEM>>>(AT, Dm, ca_wo, Dm, ca_bo, PR, Dm, Ntok, Dm, 0);
    k_ln_res<<<Ntok, blk>>>(X1, PR, n2_g, n2_b, X2);

    // ---- MoE (sparse top-2 dispatch) ----
    k_moe_init<<<1, blk>>>();
    k_router<<<Ntok, blk>>>(X2, r_w, r_b, 0);
    k_offsets<<<1, 1>>>();
    k_gather<<<Ntok, blk>>>(X2);
    k_moe_gemm_mma<<<dim3(Ntok / 128, Ff / 128, Ee), blk, GEMM_SMEM>>>(XG, e_w1, e_b1, HB, Dm, Ff, 1);
    k_moe_gemm_mma<<<dim3(Ntok / 128, Dm / 128, Ee), blk, GEMM_SMEM>>>(HB, e_w2, e_b2, YG, Ff, Dm, 0);
    k_zero_mo<<<Ntok, blk>>>();
    k_scatter<<<NKCAP, blk>>>();
    k_ln_res<<<Ntok, blk>>>(X2, (float*)pMO, n3_g, n3_b, out);

    // ---- aux loss (router recompute on OUTPUT, per reference) ----
    if (out_size > Ntok * Dm) {
        k_router<<<Ntok, blk>>>(out, r_w, r_b, 1);
        k_aux_final<<<1, blk>>>(out + (out_size - 1));
    }
}

// round 5
// speedup vs baseline: 1.0776x; 1.0776x over previous
#include <cuda_runtime.h>
#include <math.h>

// ---------------- problem constants ----------------
#define Dm      1024
#define Hh      16
#define DHd     64
#define Ff      4096
#define Ee      8
#define TOPK    2
#define Bbat    2
#define Sseq    2048
#define Ntok    4096
#define NKCAP   16384

// GEMM tiling
#define AP 36
#define BP 136
#define GEMM_ASZ (128 * AP)
#define GEMM_BSZ (32 * BP)
#define GEMM_STG (GEMM_ASZ + GEMM_BSZ)
#define GEMM_NSTAGE 3
#define GEMM_SMEM (GEMM_NSTAGE * GEMM_STG * 4)

// flash tiling (register-staged, round-3 style)
#define QT      128
#define KC      64
#define KSP     68
#define VSP     72
#define PSP     68
#define FLASH_SMEM ((KC*KSP + KC*VSP + QT*PSP) * 4)

// ---------------- device scratch ----------------
__device__ float g_Q [Ntok * Dm];
__device__ float g_K [Ntok * Dm];
__device__ float g_V [Ntok * Dm];
__device__ float g_AT[Ntok * Dm];
__device__ float g_PR[Ntok * Dm];
__device__ float g_X1[Ntok * Dm];
__device__ float g_X2[Ntok * Dm];

__device__ float g_XG[(size_t)NKCAP * Dm];
__device__ float g_HB[(size_t)NKCAP * Ff];
__device__ float g_YG[(size_t)NKCAP * Dm];
__device__ float g_MO[Ntok * Dm];

__device__ int   g_tok_e[Ntok * TOPK];
__device__ float g_tok_g[Ntok * TOPK];
__device__ int   g_cnt[Ee];
__device__ int   g_cur[Ee];
__device__ int   g_off[Ee + 1];
__device__ int   g_row_tok[NKCAP];
__device__ float g_row_gate[NKCAP];
__device__ float g_auxp[Ntok * Ee];
__device__ int   g_auxi[Ntok * TOPK];

// ---------------- helpers ----------------
__device__ __forceinline__ unsigned f2tf(float f) {
    unsigned r;
    asm("cvt.rna.tf32.f32 %0, %1;" : "=r"(r) : "f"(f));
    return r;
}

__device__ __forceinline__ void mma_tf32(float* c, const unsigned* a, const unsigned* b) {
    asm volatile(
        "mma.sync.aligned.m16n8k8.row.col.f32.tf32.tf32.f32 "
        "{%0,%1,%2,%3},{%4,%5,%6,%7},{%8,%9},{%0,%1,%2,%3};\n"
        : "+f"(c[0]), "+f"(c[1]), "+f"(c[2]), "+f"(c[3])
        : "r"(a[0]), "r"(a[1]), "r"(a[2]), "r"(a[3]), "r"(b[0]), "r"(b[1]));
}

__device__ __forceinline__ void cp16(float* smem, const float* gmem, bool pred) {
    unsigned saddr = (unsigned)__cvta_generic_to_shared(smem);
    int sz = pred ? 16 : 0;
    asm volatile("cp.async.ca.shared.global [%0], [%1], 16, %2;\n"
                 :: "r"(saddr), "l"(gmem), "r"(sz));
}
__device__ __forceinline__ void cp_commit() {
    asm volatile("cp.async.commit_group;\n");
}
__device__ __forceinline__ void cp_wait1() {
    asm volatile("cp.async.wait_group 1;\n" ::: "memory");
}

// ---------------- GEMM: 128x128x32, 3-stage cp.async, 1 sync per tile ----------------
__device__ __forceinline__ void gemm_stage(
    float* As, float* Bs,
    const float* __restrict__ A, int lda,
    const float* __restrict__ Bg, int ldb,
    int bm, int bn, int k0, int M, int tid)
{
#pragma unroll
    for (int i = 0; i < 4; i++) {
        int idx = tid + i * 256;
        int r = idx >> 3, c = (idx & 7) << 2;
        bool p = (bm + r) < M;
        const float* src = A + (size_t)(p ? (bm + r) : 0) * lda + k0 + c;
        cp16(&As[r * AP + c], src, p);
    }
#pragma unroll
    for (int i = 0; i < 4; i++) {
        int idx = tid + i * 256;
        int r = idx >> 5, c = (idx & 31) << 2;
        cp16(&Bs[r * BP + c], Bg + (size_t)(k0 + r) * ldb + bn + c, true);
    }
}

__device__ __forceinline__ void mma_gemm_tile(
    const float* __restrict__ A, int lda,
    const float* __restrict__ Bg, int ldb,
    const float* __restrict__ bias,
    float* __restrict__ C, int ldc,
    int M, int Kd, int bm, int bn, int relu)
{
    extern __shared__ float smp[];

    const int tid  = threadIdx.x;
    const int lane = tid & 31;
    const int wid  = tid >> 5;
    const int wm = (wid >> 2) * 64;
    const int wn = (wid & 3) * 32;
    const int g  = lane >> 2;
    const int tg = lane & 3;

    float acc[4][4][4];
#pragma unroll
    for (int i = 0; i < 4; i++)
#pragma unroll
        for (int j = 0; j < 4; j++)
#pragma unroll
            for (int q = 0; q < 4; q++) acc[i][j][q] = 0.f;

    const int ktiles = Kd / 32;

    gemm_stage(smp, smp + GEMM_ASZ, A, lda, Bg, ldb, bm, bn, 0, M, tid);
    cp_commit();
    gemm_stage(smp + GEMM_STG, smp + GEMM_STG + GEMM_ASZ, A, lda, Bg, ldb, bm, bn, 32, M, tid);
    cp_commit();

    for (int t = 0; t < ktiles; t++) {
        cp_wait1();
        __syncthreads();

        // prefetch tile t+2 into slot (t+2)%3 (safe: consumed at t-1, synced above)
        if (t + 2 < ktiles) {
            float* dst = smp + ((t + 2) % GEMM_NSTAGE) * GEMM_STG;
            gemm_stage(dst, dst + GEMM_ASZ, A, lda, Bg, ldb, bm, bn, (t + 2) * 32, M, tid);
        }
        cp_commit();

        const unsigned* As = (const unsigned*)(smp + (t % GEMM_NSTAGE) * GEMM_STG);
        const unsigned* Bs = As + GEMM_ASZ;

#pragma unroll
        for (int ks = 0; ks < 4; ks++) {
            const int k = ks * 8;
            unsigned af[4][4], bf[4][2];
#pragma unroll
            for (int mt = 0; mt < 4; mt++) {
                int mb = wm + mt * 16;
                af[mt][0] = As[(mb + g)     * AP + k + tg];
                af[mt][1] = As[(mb + g + 8) * AP + k + tg];
                af[mt][2] = As[(mb + g)     * AP + k + tg + 4];
                af[mt][3] = As[(mb + g + 8) * AP + k + tg + 4];
            }
#pragma unroll
            for (int nt = 0; nt < 4; nt++) {
                int nb = wn + nt * 8;
                bf[nt][0] = Bs[(k + tg)     * BP + nb + g];
                bf[nt][1] = Bs[(k + tg + 4) * BP + nb + g];
            }
#pragma unroll
            for (int mt = 0; mt < 4; mt++)
#pragma unroll
                for (int nt = 0; nt < 4; nt++)
                    mma_tf32(acc[mt][nt], af[mt], bf[nt]);
        }
    }

#pragma unroll
    for (int mt = 0; mt < 4; mt++) {
#pragma unroll
        for (int nt = 0; nt < 4; nt++) {
            int row0 = bm + wm + mt * 16 + g;
            int col  = bn + wn + nt * 8 + tg * 2;
            float b0 = bias ? bias[col]     : 0.f;
            float b1 = bias ? bias[col + 1] : 0.f;
            float v0 = acc[mt][nt][0] + b0;
            float v1 = acc[mt][nt][1] + b1;
            float v2 = acc[mt][nt][2] + b0;
            float v3 = acc[mt][nt][3] + b1;
            if (relu) {
                v0 = fmaxf(v0, 0.f); v1 = fmaxf(v1, 0.f);
                v2 = fmaxf(v2, 0.f); v3 = fmaxf(v3, 0.f);
            }
            if (row0 < M)     *(float2*)(C + (size_t)row0 * ldc + col)       = make_float2(v0, v1);
            if (row0 + 8 < M) *(float2*)(C + (size_t)(row0 + 8) * ldc + col) = make_float2(v2, v3);
        }
    }
}

__global__ void __launch_bounds__(256) k_gemm128(
    const float* __restrict__ A, int lda, const float* __restrict__ B, int ldb,
    const float* __restrict__ bias, float* __restrict__ C, int ldc, int M, int Kd, int relu)
{
    mma_gemm_tile(A, lda, B, ldb, bias, C, ldc, M, Kd,
                  blockIdx.x * 128, blockIdx.y * 128, relu);
}

__global__ void __launch_bounds__(256) k_moe_gemm_mma(
    const float* __restrict__ Abase, const float* __restrict__ Wbase,
    const float* __restrict__ bbase, float* __restrict__ Cbase, int Kd, int Nn, int relu)
{
    int e = blockIdx.z;
    int cnt = g_cnt[e];
    int bm = blockIdx.x * 128;
    if (bm >= cnt) return;
    int off = g_off[e];
    mma_gemm_tile(Abase + (size_t)off * Kd, Kd,
                  Wbase + (size_t)e * Kd * Nn, Nn,
                  bbase + (size_t)e * Nn,
                  Cbase + (size_t)off * Nn, Nn,
                  cnt, Kd, bm, blockIdx.y * 128, relu);
}

// ---------------- flash attention (round-3 register-staged version) ----------------
__global__ void __launch_bounds__(256) k_flash(
    const float* __restrict__ Qg, const float* __restrict__ Kg,
    const float* __restrict__ Vg, float* __restrict__ AT)
{
    extern __shared__ float sm[];
    unsigned* Ks = (unsigned*)sm;
    unsigned* Vs = Ks + KC * KSP;
    unsigned* Ps = Vs + KC * VSP;

    const int bh = blockIdx.y;
    const int b = bh >> 4, h = bh & 15;
    const int q0 = blockIdx.x * QT;
    const int tid = threadIdx.x;
    const int lane = tid & 31;
    const int wid = tid >> 5;
    const int g = lane >> 2;
    const int tg = lane & 3;
    const int wrow = wid * 16;

    const float* Qp = Qg + (size_t)b * Sseq * Dm + h * DHd;
    const float* Kp = Kg + (size_t)b * Sseq * Dm + h * DHd;
    const float* Vp = Vg + (size_t)b * Sseq * Dm + h * DHd;

    unsigned qf[8][4];
#pragma unroll
    for (int kt = 0; kt < 8; kt++) {
        int k = kt * 8;
        qf[kt][0] = f2tf(Qp[(size_t)(q0 + wrow + g)     * Dm + k + tg]);
        qf[kt][1] = f2tf(Qp[(size_t)(q0 + wrow + g + 8) * Dm + k + tg]);
        qf[kt][2] = f2tf(Qp[(size_t)(q0 + wrow + g)     * Dm + k + tg + 4]);
        qf[kt][3] = f2tf(Qp[(size_t)(q0 + wrow + g + 8) * Dm + k + tg + 4]);
    }

    float oacc[8][4];
#pragma unroll
    for (int i = 0; i < 8; i++)
#pragma unroll
        for (int j = 0; j < 4; j++) oacc[i][j] = 0.f;
    float m0 = -1e30f, m1 = -1e30f, l0 = 0.f, l1 = 0.f;

    for (int c = 0; c < Sseq / KC; c++) {
        int kc0 = c * KC;
#pragma unroll
        for (int i = 0; i < 4; i++) {
            int idx = tid + i * 256;
            int r = idx >> 4, cc = (idx & 15) << 2;
            float4 kv = *(const float4*)(Kp + (size_t)(kc0 + r) * Dm + cc);
            unsigned* p = &Ks[r * KSP + cc];
            p[0] = f2tf(kv.x); p[1] = f2tf(kv.y); p[2] = f2tf(kv.z); p[3] = f2tf(kv.w);
            float4 vv = *(const float4*)(Vp + (size_t)(kc0 + r) * Dm + cc);
            unsigned* q = &Vs[r * VSP + cc];
            q[0] = f2tf(vv.x); q[1] = f2tf(vv.y); q[2] = f2tf(vv.z); q[3] = f2tf(vv.w);
        }
        __syncthreads();

        float sacc[8][4];
#pragma unroll
        for (int i = 0; i < 8; i++)
#pragma unroll
            for (int j = 0; j < 4; j++) sacc[i][j] = 0.f;
#pragma unroll
        for (int kt = 0; kt < 8; kt++) {
            int k = kt * 8;
            unsigned bf[8][2];
#pragma unroll
            for (int nt = 0; nt < 8; nt++) {
                bf[nt][0] = Ks[(nt * 8 + g) * KSP + k + tg];
                bf[nt][1] = Ks[(nt * 8 + g) * KSP + k + tg + 4];
            }
#pragma unroll
            for (int nt = 0; nt < 8; nt++)
                mma_tf32(sacc[nt], qf[kt], bf[nt]);
        }

        float mx0 = -1e30f, mx1 = -1e30f;
#pragma unroll
        for (int nt = 0; nt < 8; nt++) {
            sacc[nt][0] *= 0.125f; sacc[nt][1] *= 0.125f;
            sacc[nt][2] *= 0.125f; sacc[nt][3] *= 0.125f;
            mx0 = fmaxf(mx0, fmaxf(sacc[nt][0], sacc[nt][1]));
            mx1 = fmaxf(mx1, fmaxf(sacc[nt][2], sacc[nt][3]));
        }
        mx0 = fmaxf(mx0, __shfl_xor_sync(0xffffffff, mx0, 1));
        mx0 = fmaxf(mx0, __shfl_xor_sync(0xffffffff, mx0, 2));
        mx1 = fmaxf(mx1, __shfl_xor_sync(0xffffffff, mx1, 1));
        mx1 = fmaxf(mx1, __shfl_xor_sync(0xffffffff, mx1, 2));
        float nm0 = fmaxf(m0, mx0), nm1 = fmaxf(m1, mx1);
        float sc0 = __expf(m0 - nm0), sc1 = __expf(m1 - nm1);
        float ps0 = 0.f, ps1 = 0.f;
#pragma unroll
        for (int nt = 0; nt < 8; nt++) {
            float p00 = __expf(sacc[nt][0] - nm0);
            float p01 = __expf(sacc[nt][1] - nm0);
            float p10 = __expf(sacc[nt][2] - nm1);
            float p11 = __expf(sacc[nt][3] - nm1);
            ps0 += p00 + p01; ps1 += p10 + p11;
            int col = nt * 8 + tg * 2;
            *(uint2*)&Ps[(wrow + g)     * PSP + col] = make_uint2(f2tf(p00), f2tf(p01));
            *(uint2*)&Ps[(wrow + g + 8) * PSP + col] = make_uint2(f2tf(p10), f2tf(p11));
        }
        ps0 += __shfl_xor_sync(0xffffffff, ps0, 1);
        ps0 += __shfl_xor_sync(0xffffffff, ps0, 2);
        ps1 += __shfl_xor_sync(0xffffffff, ps1, 1);
        ps1 += __shfl_xor_sync(0xffffffff, ps1, 2);
        l0 = l0 * sc0 + ps0; l1 = l1 * sc1 + ps1;
        m0 = nm0; m1 = nm1;
#pragma unroll
        for (int nt = 0; nt < 8; nt++) {
            oacc[nt][0] *= sc0; oacc[nt][1] *= sc0;
            oacc[nt][2] *= sc1; oacc[nt][3] *= sc1;
        }
        __syncwarp();

#pragma unroll
        for (int kt = 0; kt < 8; kt++) {
            int k = kt * 8;
            unsigned af[4];
            af[0] = Ps[(wrow + g)     * PSP + k + tg];
            af[1] = Ps[(wrow + g + 8) * PSP + k + tg];
            af[2] = Ps[(wrow + g)     * PSP + k + tg + 4];
            af[3] = Ps[(wrow + g + 8) * PSP + k + tg + 4];
            unsigned bf[8][2];
#pragma unroll
            for (int nt = 0; nt < 8; nt++) {
                bf[nt][0] = Vs[(k + tg)     * VSP + nt * 8 + g];
                bf[nt][1] = Vs[(k + tg + 4) * VSP + nt * 8 + g];
            }
#pragma unroll
            for (int nt = 0; nt < 8; nt++)
                mma_tf32(oacc[nt], af, bf[nt]);
        }
        __syncthreads();
    }

    float inv0 = 1.f / l0, inv1 = 1.f / l1;
    float* Op = AT + (size_t)b * Sseq * Dm + h * DHd;
#pragma unroll
    for (int nt = 0; nt < 8; nt++) {
        int col = nt * 8 + tg * 2;
        *(float2*)(Op + (size_t)(q0 + wrow + g) * Dm + col) =
            make_float2(oacc[nt][0] * inv0, oacc[nt][1] * inv0);
        *(float2*)(Op + (size_t)(q0 + wrow + g + 8) * Dm + col) =
            make_float2(oacc[nt][2] * inv1, oacc[nt][3] * inv1);
    }
}

// ---------------- layernorm(residual) ----------------
__global__ void k_ln_res(const float* __restrict__ X, const float* __restrict__ R,
                         const float* __restrict__ gw, const float* __restrict__ bw,
                         float* __restrict__ O)
{
    int t = blockIdx.x, tid = threadIdx.x;
    const float* xp = X + (size_t)t * Dm;
    const float* rp = R + (size_t)t * Dm;
    float v[4]; float s = 0.f;
#pragma unroll
    for (int i = 0; i < 4; i++) { int d = tid + i * 256; v[i] = xp[d] + rp[d]; s += v[i]; }
    __shared__ float red[256];
    red[tid] = s; __syncthreads();
    for (int st = 128; st > 0; st >>= 1) {
        if (tid < st) red[tid] += red[tid + st];
        __syncthreads();
    }
    float mean = red[0] * (1.f / Dm);
    __syncthreads();
    float s2 = 0.f;
#pragma unroll
    for (int i = 0; i < 4; i++) { float dd = v[i] - mean; s2 += dd * dd; }
    red[tid] = s2; __syncthreads();
    for (int st = 128; st > 0; st >>= 1) {
        if (tid < st) red[tid] += red[tid + st];
        __syncthreads();
    }
    float rstd = rsqrtf(red[0] * (1.f / Dm) + 1e-5f);
    float* op = O + (size_t)t * Dm;
#pragma unroll
    for (int i = 0; i < 4; i++) {
        int d = tid + i * 256;
        op[d] = (v[i] - mean) * rstd * gw[d] + bw[d];
    }
}

// ---------------- MoE routing / dispatch ----------------
__global__ void k_moe_init()
{
    int tid = threadIdx.x;
    if (tid < Ee) { g_cnt[tid] = 0; g_cur[tid] = 0; }
    for (int i = tid; i < NKCAP; i += 256) g_row_tok[i] = -1;
}

__global__ void k_router(const float* __restrict__ X,
                         const float* __restrict__ rw,
                         const float* __restrict__ rb,
                         int mode)
{
    int t = blockIdx.x, tid = threadIdx.x;
    const float* xp = X + (size_t)t * Dm;
    float loc[Ee];
#pragma unroll
    for (int e = 0; e < Ee; e++) loc[e] = 0.f;
    for (int d = tid; d < Dm; d += 256) {
        float xv = xp[d];
#pragma unroll
        for (int e = 0; e < Ee; e++) loc[e] += xv * rw[d * Ee + e];
    }
    __shared__ float red[256 * Ee];
#pragma unroll
    for (int e = 0; e < Ee; e++) red[tid * Ee + e] = loc[e];
    __syncthreads();
    for (int st = 128; st > 0; st >>= 1) {
        if (tid < st)
#pragma unroll
            for (int e = 0; e < Ee; e++)
                red[tid * Ee + e] += red[(tid + st) * Ee + e];
        __syncthreads();
    }
    if (tid == 0) {
        float lg[Ee], mx = -1e30f;
#pragma unroll
        for (int e = 0; e < Ee; e++) { lg[e] = red[e] + rb[e]; mx = fmaxf(mx, lg[e]); }
        float sm = 0.f;
#pragma unroll
        for (int e = 0; e < Ee; e++) { lg[e] = expf(lg[e] - mx); sm += lg[e]; }
        float inv = 1.f / sm;
#pragma unroll
        for (int e = 0; e < Ee; e++) lg[e] *= inv;
        int e0 = 0;
#pragma unroll
        for (int e = 1; e < Ee; e++) if (lg[e] > lg[e0]) e0 = e;
        int e1 = -1;
#pragma unroll
        for (int e = 0; e < Ee; e++)
            if (e != e0 && (e1 < 0 || lg[e] > lg[e1])) e1 = e;
        if (mode == 0) {
            float g0 = lg[e0], g1 = lg[e1], gs = g0 + g1;
            g_tok_e[t * 2] = e0;  g_tok_e[t * 2 + 1] = e1;
            g_tok_g[t * 2] = g0 / gs; g_tok_g[t * 2 + 1] = g1 / gs;
            atomicAdd(&g_cnt[e0], 1); atomicAdd(&g_cnt[e1], 1);
        } else {
#pragma unroll
            for (int e = 0; e < Ee; e++) g_auxp[t * Ee + e] = lg[e];
            g_auxi[t * 2] = e0; g_auxi[t * 2 + 1] = e1;
        }
    }
}

__global__ void k_offsets()
{
    if (threadIdx.x == 0) {
        int acc = 0;
        for (int e = 0; e < Ee; e++) {
            g_off[e] = acc;
            acc += ((g_cnt[e] + 127) >> 7) << 7;
        }
        g_off[Ee] = acc;
    }
}

__global__ void k_gather(const float* __restrict__ X)
{
    int t = blockIdx.x, tid = threadIdx.x;
    __shared__ int spos[TOPK];
    if (tid == 0) {
#pragma unroll
        for (int k = 0; k < TOPK; k++) {
            int e = g_tok_e[t * 2 + k];
            int p = g_off[e] + atomicAdd(&g_cur[e], 1);
            spos[k] = p;
            g_row_tok[p] = t;
            g_row_gate[p] = g_tok_g[t * 2 + k];
        }
    }
    __syncthreads();
    const float4* src = reinterpret_cast<const float4*>(X + (size_t)t * Dm);
#pragma unroll
    for (int k = 0; k < TOPK; k++) {
        float4* dst = reinterpret_cast<float4*>(g_XG + (size_t)spos[k] * Dm);
        dst[tid] = src[tid];
    }
}

__global__ void k_zero_mo()
{
    int t = blockIdx.x, tid = threadIdx.x;
    float4 z = make_float4(0.f, 0.f, 0.f, 0.f);
    reinterpret_cast<float4*>(g_MO + (size_t)t * Dm)[tid] = z;
}

__global__ void k_scatter()
{
    int p = blockIdx.x;
    int t = g_row_tok[p];
    if (t < 0) return;
    float gt = g_row_gate[p];
    int tid = threadIdx.x;
    for (int d = tid; d < Dm; d += 256)
        atomicAdd(&g_MO[(size_t)t * Dm + d], gt * g_YG[(size_t)p * Dm + d]);
}

__global__ void k_aux_final(float* __restrict__ out)
{
    int tid = threadIdx.x;
    float imp[Ee];
#pragma unroll
    for (int e = 0; e < Ee; e++) imp[e] = 0.f;
    for (int t = tid; t < Ntok; t += 256)
#pragma unroll
        for (int e = 0; e < Ee; e++) imp[e] += g_auxp[t * Ee + e];
    float ld[Ee];
#pragma unroll
    for (int e = 0; e < Ee; e++) ld[e] = 0.f;
    for (int i = tid; i < Ntok * TOPK; i += 256) ld[g_auxi[i]] += 1.f;

    __shared__ float red[256 * Ee];
    __shared__ float simp[Ee];
#pragma unroll
    for (int e = 0; e < Ee; e++) red[tid * Ee + e] = imp[e];
    __syncthreads();
    for (int st = 128; st > 0; st >>= 1) {
        if (tid < st)
#pragma unroll
            for (int e = 0; e < Ee; e++)
                red[tid * Ee + e] += red[(tid + st) * Ee + e];
        __syncthreads();
    }
    if (tid == 0)
#pragma unroll
        for (int e = 0; e < Ee; e++) simp[e] = red[e];
    __syncthreads();
#pragma unroll
    for (int e = 0; e < Ee; e++) red[tid * Ee + e] = ld[e];
    __syncthreads();
    for (int st = 128; st > 0; st >>= 1) {
        if (tid < st)
#pragma unroll
            for (int e = 0; e < Ee; e++)
                red[tid * Ee + e] += red[(tid + st) * Ee + e];
        __syncthreads();
    }
    if (tid == 0) {
        float aux = 0.f;
#pragma unroll
        for (int e = 0; e < Ee; e++)
            aux += (simp[e] / (float)Ntok) * (red[e] / (float)(Ntok * TOPK));
        out[0] = (float)Ee * aux;
    }
}

// ---------------- host orchestration ----------------
extern "C" void kernel_launch(void* const* d_in, const int* in_sizes, int n_in,
                              void* d_out, int out_size)
{
    (void)in_sizes; (void)n_in;
    const float* x     = (const float*)d_in[0];
    const float* enc   = (const float*)d_in[1];
    const float* sa_wq = (const float*)d_in[2];
    const float* sa_bq = (const float*)d_in[3];
    const float* sa_wk = (const float*)d_in[4];
    const float* sa_bk = (const float*)d_in[5];
    const float* sa_wv = (const float*)d_in[6];
    const float* sa_bv = (const float*)d_in[7];
    const float* sa_wo = (const float*)d_in[8];
    const float* sa_bo = (const float*)d_in[9];
    const float* ca_wq = (const float*)d_in[10];
    const float* ca_bq = (const float*)d_in[11];
    const float* ca_wk = (const float*)d_in[12];
    const float* ca_bk = (const float*)d_in[13];
    const float* ca_wv = (const float*)d_in[14];
    const float* ca_bv = (const float*)d_in[15];
    const float* ca_wo = (const float*)d_in[16];
    const float* ca_bo = (const float*)d_in[17];
    const float* n1_g  = (const float*)d_in[18];
    const float* n1_b  = (const float*)d_in[19];
    const float* n2_g  = (const float*)d_in[20];
    const float* n2_b  = (const float*)d_in[21];
    const float* n3_g  = (const float*)d_in[22];
    const float* n3_b  = (const float*)d_in[23];
    const float* r_w   = (const float*)d_in[24];
    const float* r_b   = (const float*)d_in[25];
    const float* e_w1  = (const float*)d_in[26];
    const float* e_b1  = (const float*)d_in[27];
    const float* e_w2  = (const float*)d_in[28];
    const float* e_b2  = (const float*)d_in[29];

    void *pQ, *pK, *pV, *pAT, *pPR, *pX1, *pX2, *pXG, *pHB, *pYG, *pMO;
    cudaGetSymbolAddress(&pQ,  g_Q);
    cudaGetSymbolAddress(&pK,  g_K);
    cudaGetSymbolAddress(&pV,  g_V);
    cudaGetSymbolAddress(&pAT, g_AT);
    cudaGetSymbolAddress(&pPR, g_PR);
    cudaGetSymbolAddress(&pX1, g_X1);
    cudaGetSymbolAddress(&pX2, g_X2);
    cudaGetSymbolAddress(&pXG, g_XG);
    cudaGetSymbolAddress(&pHB, g_HB);
    cudaGetSymbolAddress(&pYG, g_YG);
    cudaGetSymbolAddress(&pMO, g_MO);
    float* Q  = (float*)pQ;  float* K  = (float*)pK;  float* V  = (float*)pV;
    float* AT = (float*)pAT; float* PR = (float*)pPR;
    float* X1 = (float*)pX1; float* X2 = (float*)pX2;
    float* XG = (float*)pXG; float* HB = (float*)pHB; float* YG = (float*)pYG;
    float* out = (float*)d_out;

    static int smem_set = 0;
    if (!smem_set) {
        cudaFuncSetAttribute(k_flash, cudaFuncAttributeMaxDynamicSharedMemorySize, FLASH_SMEM);
        cudaFuncSetAttribute(k_gemm128, cudaFuncAttributeMaxDynamicSharedMemorySize, GEMM_SMEM);
        cudaFuncSetAttribute(k_moe_gemm_mma, cudaFuncAttributeMaxDynamicSharedMemorySize, GEMM_SMEM);
        smem_set = 1;
    }

    dim3 blk(256);
    dim3 gProj(Ntok / 128, Dm / 128);
    dim3 gFlash(Sseq / QT, Bbat * Hh);

    // ---- self attention ----
    k_gemm128<<<gProj, blk, GEMM_SMEM>>>(x, Dm, sa_wq, Dm, sa_bq, Q, Dm, Ntok, Dm, 0);
    k_gemm128<<<gProj, blk, GEMM_SMEM>>>(x, Dm, sa_wk, Dm, sa_bk, K, Dm, Ntok, Dm, 0);
    k_gemm128<<<gProj, blk, GEMM_SMEM>>>(x, Dm, sa_wv, Dm, sa_bv, V, Dm, Ntok, Dm, 0);
    k_flash<<<gFlash, blk, FLASH_SMEM>>>(Q, K, V, AT);
    k_gemm128<<<gProj, blk, GEMM_SMEM>>>(AT, Dm, sa_wo, Dm, sa_bo, PR, Dm, Ntok, Dm, 0);
    k_ln_res<<<Ntok, blk>>>(x, PR, n1_g, n1_b, X1);

    // ---- cross attention ----
    k_gemm128<<<gProj, blk, GEMM_SMEM>>>(X1,  Dm, ca_wq, Dm, ca_bq, Q, Dm, Ntok, Dm, 0);
    k_gemm128<<<gProj, blk, GEMM_SMEM>>>(enc, Dm, ca_wk, Dm, ca_bk, K, Dm, Ntok, Dm, 0);
    k_gemm128<<<gProj, blk, GEMM_SMEM>>>(enc, Dm, ca_wv, Dm, ca_bv, V, Dm, Ntok, Dm, 0);
    k_flash<<<gFlash, blk, FLASH_SMEM>>>(Q, K, V, AT);
    k_gemm128<<<gProj, blk, GEMM_SMEM>>>(AT, Dm, ca_wo, Dm, ca_bo, PR, Dm, Ntok, Dm, 0);
    k_ln_res<<<Ntok, blk>>>(X1, PR, n2_g, n2_b, X2);

    // ---- MoE (sparse top-2 dispatch) ----
    k_moe_init<<<1, blk>>>();
    k_router<<<Ntok, blk>>>(X2, r_w, r_b, 0);
    k_offsets<<<1, 1>>>();
    k_gather<<<Ntok, blk>>>(X2);
    k_moe_gemm_mma<<<dim3(Ntok / 128, Ff / 128, Ee), blk, GEMM_SMEM>>>(XG, e_w1, e_b1, HB, Dm, Ff, 1);
    k_moe_gemm_mma<<<dim3(Ntok / 128, Dm / 128, Ee), blk, GEMM_SMEM>>>(HB, e_w2, e_b2, YG, Ff, Dm, 0);
    k_zero_mo<<<Ntok, blk>>>();
    k_scatter<<<NKCAP, blk>>>();
    k_ln_res<<<Ntok, blk>>>(X2, (float*)pMO, n3_g, n3_b, out);

    // ---- aux loss (router recompute on OUTPUT, per reference) ----
    if (out_size > Ntok * Dm) {
        k_router<<<Ntok, blk>>>(out, r_w, r_b, 1);
        k_aux_final<<<1, blk>>>(out + (out_size - 1));
    }
}

// round 6
// speedup vs baseline: 1.1346x; 1.0529x over previous
#include <cuda_runtime.h>
#include <math.h>

// ---------------- problem constants ----------------
#define Dm      1024
#define Hh      16
#define DHd     64
#define Ff      4096
#define Ee      8
#define TOPK    2
#define Bbat    2
#define Sseq    2048
#define Ntok    4096
#define NKCAP   16384

// GEMM tiling: 128x128x32 tile, 128 threads (4 warps of 64x64)
#define AP 36
#define BP 136
#define GEMM_ASZ (128 * AP)
#define GEMM_BSZ (32 * BP)
#define GEMM_STG (GEMM_ASZ + GEMM_BSZ)
#define GEMM_NSTAGE 3
#define GEMM_SMEM (GEMM_NSTAGE * GEMM_STG * 4)

// flash tiling (register-staged, proven round-3 version)
#define QT      128
#define KC      64
#define KSP     68
#define VSP     72
#define PSP     68
#define FLASH_SMEM ((KC*KSP + KC*VSP + QT*PSP) * 4)

// ---------------- device scratch ----------------
__device__ float g_Q [Ntok * Dm];
__device__ float g_K [Ntok * Dm];
__device__ float g_V [Ntok * Dm];
__device__ float g_AT[Ntok * Dm];
__device__ float g_PR[Ntok * Dm];
__device__ float g_X1[Ntok * Dm];
__device__ float g_X2[Ntok * Dm];

__device__ float g_XG[(size_t)NKCAP * Dm];
__device__ float g_HB[(size_t)NKCAP * Ff];
__device__ float g_YG[(size_t)NKCAP * Dm];

__device__ int   g_tok_e[Ntok * TOPK];
__device__ float g_tok_g[Ntok * TOPK];
__device__ int   g_tok_pos[Ntok * TOPK];
__device__ int   g_cnt[Ee];
__device__ int   g_cur[Ee];
__device__ int   g_off[Ee + 1];
__device__ float g_auxp[Ntok * Ee];
__device__ int   g_auxi[Ntok * TOPK];

// ---------------- helpers ----------------
__device__ __forceinline__ unsigned f2tf(float f) {
    unsigned r;
    asm("cvt.rna.tf32.f32 %0, %1;" : "=r"(r) : "f"(f));
    return r;
}

__device__ __forceinline__ void mma_tf32(float* c, const unsigned* a, const unsigned* b) {
    asm volatile(
        "mma.sync.aligned.m16n8k8.row.col.f32.tf32.tf32.f32 "
        "{%0,%1,%2,%3},{%4,%5,%6,%7},{%8,%9},{%0,%1,%2,%3};\n"
        : "+f"(c[0]), "+f"(c[1]), "+f"(c[2]), "+f"(c[3])
        : "r"(a[0]), "r"(a[1]), "r"(a[2]), "r"(a[3]), "r"(b[0]), "r"(b[1]));
}

__device__ __forceinline__ void cp16(float* smem, const float* gmem, bool pred) {
    unsigned saddr = (unsigned)__cvta_generic_to_shared(smem);
    int sz = pred ? 16 : 0;
    asm volatile("cp.async.ca.shared.global [%0], [%1], 16, %2;\n"
                 :: "r"(saddr), "l"(gmem), "r"(sz));
}
__device__ __forceinline__ void cp_commit() {
    asm volatile("cp.async.commit_group;\n");
}
__device__ __forceinline__ void cp_wait1() {
    asm volatile("cp.async.wait_group 1;\n" ::: "memory");
}

// ---------------- GEMM: 128x128x32, 128 threads, warp tile 64x64 ----------------
__device__ __forceinline__ void gemm_stage(
    float* As, float* Bs,
    const float* __restrict__ A, int lda,
    const float* __restrict__ Bg, int ldb,
    int bm, int bn, int k0, int M, int tid)
{
#pragma unroll
    for (int i = 0; i < 8; i++) {
        int idx = tid + i * 128;
        int r = idx >> 3, c = (idx & 7) << 2;
        bool p = (bm + r) < M;
        const float* src = A + (size_t)(p ? (bm + r) : 0) * lda + k0 + c;
        cp16(&As[r * AP + c], src, p);
    }
#pragma unroll
    for (int i = 0; i < 8; i++) {
        int idx = tid + i * 128;
        int r = idx >> 5, c = (idx & 31) << 2;
        cp16(&Bs[r * BP + c], Bg + (size_t)(k0 + r) * ldb + bn + c, true);
    }
}

__device__ __forceinline__ void mma_gemm_tile(
    const float* __restrict__ A, int lda,
    const float* __restrict__ Bg, int ldb,
    const float* __restrict__ bias,
    float* __restrict__ C, int ldc,
    int M, int Kd, int bm, int bn, int relu)
{
    extern __shared__ float smp[];

    const int tid  = threadIdx.x;
    const int lane = tid & 31;
    const int wid  = tid >> 5;
    const int wm = (wid >> 1) * 64;
    const int wn = (wid & 1) * 64;
    const int g  = lane >> 2;
    const int tg = lane & 3;

    float acc[4][8][4];
#pragma unroll
    for (int i = 0; i < 4; i++)
#pragma unroll
        for (int j = 0; j < 8; j++)
#pragma unroll
            for (int q = 0; q < 4; q++) acc[i][j][q] = 0.f;

    const int ktiles = Kd / 32;

    gemm_stage(smp, smp + GEMM_ASZ, A, lda, Bg, ldb, bm, bn, 0, M, tid);
    cp_commit();
    gemm_stage(smp + GEMM_STG, smp + GEMM_STG + GEMM_ASZ, A, lda, Bg, ldb, bm, bn, 32, M, tid);
    cp_commit();

    for (int t = 0; t < ktiles; t++) {
        cp_wait1();
        __syncthreads();

        if (t + 2 < ktiles) {
            float* dst = smp + ((t + 2) % GEMM_NSTAGE) * GEMM_STG;
            gemm_stage(dst, dst + GEMM_ASZ, A, lda, Bg, ldb, bm, bn, (t + 2) * 32, M, tid);
        }
        cp_commit();

        const unsigned* As = (const unsigned*)(smp + (t % GEMM_NSTAGE) * GEMM_STG);
        const unsigned* Bs = As + GEMM_ASZ;

#pragma unroll
        for (int ks = 0; ks < 4; ks++) {
            const int k = ks * 8;
            unsigned af[4][4], bf[8][2];
#pragma unroll
            for (int mt = 0; mt < 4; mt++) {
                int mb = wm + mt * 16;
                af[mt][0] = As[(mb + g)     * AP + k + tg];
                af[mt][1] = As[(mb + g + 8) * AP + k + tg];
                af[mt][2] = As[(mb + g)     * AP + k + tg + 4];
                af[mt][3] = As[(mb + g + 8) * AP + k + tg + 4];
            }
#pragma unroll
            for (int nt = 0; nt < 8; nt++) {
                int nb = wn + nt * 8;
                bf[nt][0] = Bs[(k + tg)     * BP + nb + g];
                bf[nt][1] = Bs[(k + tg + 4) * BP + nb + g];
            }
#pragma unroll
            for (int mt = 0; mt < 4; mt++)
#pragma unroll
                for (int nt = 0; nt < 8; nt++)
                    mma_tf32(acc[mt][nt], af[mt], bf[nt]);
        }
    }

#pragma unroll
    for (int mt = 0; mt < 4; mt++) {
#pragma unroll
        for (int nt = 0; nt < 8; nt++) {
            int row0 = bm + wm + mt * 16 + g;
            int col  = bn + wn + nt * 8 + tg * 2;
            float b0 = bias ? bias[col]     : 0.f;
            float b1 = bias ? bias[col + 1] : 0.f;
            float v0 = acc[mt][nt][0] + b0;
            float v1 = acc[mt][nt][1] + b1;
            float v2 = acc[mt][nt][2] + b0;
            float v3 = acc[mt][nt][3] + b1;
            if (relu) {
                v0 = fmaxf(v0, 0.f); v1 = fmaxf(v1, 0.f);
                v2 = fmaxf(v2, 0.f); v3 = fmaxf(v3, 0.f);
            }
            if (row0 < M)     *(float2*)(C + (size_t)row0 * ldc + col)       = make_float2(v0, v1);
            if (row0 + 8 < M) *(float2*)(C + (size_t)(row0 + 8) * ldc + col) = make_float2(v2, v3);
        }
    }
}

__global__ void __launch_bounds__(128) k_gemm128(
    const float* __restrict__ A, int lda, const float* __restrict__ B, int ldb,
    const float* __restrict__ bias, float* __restrict__ C, int ldc, int M, int Kd, int relu)
{
    mma_gemm_tile(A, lda, B, ldb, bias, C, ldc, M, Kd,
                  blockIdx.x * 128, blockIdx.y * 128, relu);
}

__global__ void __launch_bounds__(128) k_moe_gemm_mma(
    const float* __restrict__ Abase, const float* __restrict__ Wbase,
    const float* __restrict__ bbase, float* __restrict__ Cbase, int Kd, int Nn, int relu)
{
    int e = blockIdx.z;
    int cnt = g_cnt[e];
    int bm = blockIdx.x * 128;
    if (bm >= cnt) return;
    int off = g_off[e];
    mma_gemm_tile(Abase + (size_t)off * Kd, Kd,
                  Wbase + (size_t)e * Kd * Nn, Nn,
                  bbase + (size_t)e * Nn,
                  Cbase + (size_t)off * Nn, Nn,
                  cnt, Kd, bm, blockIdx.y * 128, relu);
}

// ---------------- flash attention (register-staged, proven) ----------------
__global__ void __launch_bounds__(256) k_flash(
    const float* __restrict__ Qg, const float* __restrict__ Kg,
    const float* __restrict__ Vg, float* __restrict__ AT)
{
    extern __shared__ float sm[];
    unsigned* Ks = (unsigned*)sm;
    unsigned* Vs = Ks + KC * KSP;
    unsigned* Ps = Vs + KC * VSP;

    const int bh = blockIdx.y;
    const int b = bh >> 4, h = bh & 15;
    const int q0 = blockIdx.x * QT;
    const int tid = threadIdx.x;
    const int lane = tid & 31;
    const int wid = tid >> 5;
    const int g = lane >> 2;
    const int tg = lane & 3;
    const int wrow = wid * 16;

    const float* Qp = Qg + (size_t)b * Sseq * Dm + h * DHd;
    const float* Kp = Kg + (size_t)b * Sseq * Dm + h * DHd;
    const float* Vp = Vg + (size_t)b * Sseq * Dm + h * DHd;

    unsigned qf[8][4];
#pragma unroll
    for (int kt = 0; kt < 8; kt++) {
        int k = kt * 8;
        qf[kt][0] = f2tf(Qp[(size_t)(q0 + wrow + g)     * Dm + k + tg]);
        qf[kt][1] = f2tf(Qp[(size_t)(q0 + wrow + g + 8) * Dm + k + tg]);
        qf[kt][2] = f2tf(Qp[(size_t)(q0 + wrow + g)     * Dm + k + tg + 4]);
        qf[kt][3] = f2tf(Qp[(size_t)(q0 + wrow + g + 8) * Dm + k + tg + 4]);
    }

    float oacc[8][4];
#pragma unroll
    for (int i = 0; i < 8; i++)
#pragma unroll
        for (int j = 0; j < 4; j++) oacc[i][j] = 0.f;
    float m0 = -1e30f, m1 = -1e30f, l0 = 0.f, l1 = 0.f;

    for (int c = 0; c < Sseq / KC; c++) {
        int kc0 = c * KC;
#pragma unroll
        for (int i = 0; i < 4; i++) {
            int idx = tid + i * 256;
            int r = idx >> 4, cc = (idx & 15) << 2;
            float4 kv = *(const float4*)(Kp + (size_t)(kc0 + r) * Dm + cc);
            unsigned* p = &Ks[r * KSP + cc];
            p[0] = f2tf(kv.x); p[1] = f2tf(kv.y); p[2] = f2tf(kv.z); p[3] = f2tf(kv.w);
            float4 vv = *(const float4*)(Vp + (size_t)(kc0 + r) * Dm + cc);
            unsigned* q = &Vs[r * VSP + cc];
            q[0] = f2tf(vv.x); q[1] = f2tf(vv.y); q[2] = f2tf(vv.z); q[3] = f2tf(vv.w);
        }
        __syncthreads();

        float sacc[8][4];
#pragma unroll
        for (int i = 0; i < 8; i++)
#pragma unroll
            for (int j = 0; j < 4; j++) sacc[i][j] = 0.f;
#pragma unroll
        for (int kt = 0; kt < 8; kt++) {
            int k = kt * 8;
            unsigned bf[8][2];
#pragma unroll
            for (int nt = 0; nt < 8; nt++) {
                bf[nt][0] = Ks[(nt * 8 + g) * KSP + k + tg];
                bf[nt][1] = Ks[(nt * 8 + g) * KSP + k + tg + 4];
            }
#pragma unroll
            for (int nt = 0; nt < 8; nt++)
                mma_tf32(sacc[nt], qf[kt], bf[nt]);
        }

        float mx0 = -1e30f, mx1 = -1e30f;
#pragma unroll
        for (int nt = 0; nt < 8; nt++) {
            sacc[nt][0] *= 0.125f; sacc[nt][1] *= 0.125f;
            sacc[nt][2] *= 0.125f; sacc[nt][3] *= 0.125f;
            mx0 = fmaxf(mx0, fmaxf(sacc[nt][0], sacc[nt][1]));
            mx1 = fmaxf(mx1, fmaxf(sacc[nt][2], sacc[nt][3]));
        }
        mx0 = fmaxf(mx0, __shfl_xor_sync(0xffffffff, mx0, 1));
        mx0 = fmaxf(mx0, __shfl_xor_sync(0xffffffff, mx0, 2));
        mx1 = fmaxf(mx1, __shfl_xor_sync(0xffffffff, mx1, 1));
        mx1 = fmaxf(mx1, __shfl_xor_sync(0xffffffff, mx1, 2));
        float nm0 = fmaxf(m0, mx0), nm1 = fmaxf(m1, mx1);
        float sc0 = __expf(m0 - nm0), sc1 = __expf(m1 - nm1);
        float ps0 = 0.f, ps1 = 0.f;
#pragma unroll
        for (int nt = 0; nt < 8; nt++) {
            float p00 = __expf(sacc[nt][0] - nm0);
            float p01 = __expf(sacc[nt][1] - nm0);
            float p10 = __expf(sacc[nt][2] - nm1);
            float p11 = __expf(sacc[nt][3] - nm1);
            ps0 += p00 + p01; ps1 += p10 + p11;
            int col = nt * 8 + tg * 2;
            *(uint2*)&Ps[(wrow + g)     * PSP + col] = make_uint2(f2tf(p00), f2tf(p01));
            *(uint2*)&Ps[(wrow + g + 8) * PSP + col] = make_uint2(f2tf(p10), f2tf(p11));
        }
        ps0 += __shfl_xor_sync(0xffffffff, ps0, 1);
        ps0 += __shfl_xor_sync(0xffffffff, ps0, 2);
        ps1 += __shfl_xor_sync(0xffffffff, ps1, 1);
        ps1 += __shfl_xor_sync(0xffffffff, ps1, 2);
        l0 = l0 * sc0 + ps0; l1 = l1 * sc1 + ps1;
        m0 = nm0; m1 = nm1;
#pragma unroll
        for (int nt = 0; nt < 8; nt++) {
            oacc[nt][0] *= sc0; oacc[nt][1] *= sc0;
            oacc[nt][2] *= sc1; oacc[nt][3] *= sc1;
        }
        __syncwarp();

#pragma unroll
        for (int kt = 0; kt < 8; kt++) {
            int k = kt * 8;
            unsigned af[4];
            af[0] = Ps[(wrow + g)     * PSP + k + tg];
            af[1] = Ps[(wrow + g + 8) * PSP + k + tg];
            af[2] = Ps[(wrow + g)     * PSP + k + tg + 4];
            af[3] = Ps[(wrow + g + 8) * PSP + k + tg + 4];
            unsigned bf[8][2];
#pragma unroll
            for (int nt = 0; nt < 8; nt++) {
                bf[nt][0] = Vs[(k + tg)     * VSP + nt * 8 + g];
                bf[nt][1] = Vs[(k + tg + 4) * VSP + nt * 8 + g];
            }
#pragma unroll
            for (int nt = 0; nt < 8; nt++)
                mma_tf32(oacc[nt], af, bf[nt]);
        }
        __syncthreads();
    }

    float inv0 = 1.f / l0, inv1 = 1.f / l1;
    float* Op = AT + (size_t)b * Sseq * Dm + h * DHd;
#pragma unroll
    for (int nt = 0; nt < 8; nt++) {
        int col = nt * 8 + tg * 2;
        *(float2*)(Op + (size_t)(q0 + wrow + g) * Dm + col) =
            make_float2(oacc[nt][0] * inv0, oacc[nt][1] * inv0);
        *(float2*)(Op + (size_t)(q0 + wrow + g + 8) * Dm + col) =
            make_float2(oacc[nt][2] * inv1, oacc[nt][3] * inv1);
    }
}

// ---------------- layernorm(residual) ----------------
__global__ void k_ln_res(const float* __restrict__ X, const float* __restrict__ R,
                         const float* __restrict__ gw, const float* __restrict__ bw,
                         float* __restrict__ O)
{
    int t = blockIdx.x, tid = threadIdx.x;
    const float* xp = X + (size_t)t * Dm;
    const float* rp = R + (size_t)t * Dm;
    float v[4]; float s = 0.f;
#pragma unroll
    for (int i = 0; i < 4; i++) { int d = tid + i * 256; v[i] = xp[d] + rp[d]; s += v[i]; }
    __shared__ float red[256];
    red[tid] = s; __syncthreads();
    for (int st = 128; st > 0; st >>= 1) {
        if (tid < st) red[tid] += red[tid + st];
        __syncthreads();
    }
    float mean = red[0] * (1.f / Dm);
    __syncthreads();
    float s2 = 0.f;
#pragma unroll
    for (int i = 0; i < 4; i++) { float dd = v[i] - mean; s2 += dd * dd; }
    red[tid] = s2; __syncthreads();
    for (int st = 128; st > 0; st >>= 1) {
        if (tid < st) red[tid] += red[tid + st];
        __syncthreads();
    }
    float rstd = rsqrtf(red[0] * (1.f / Dm) + 1e-5f);
    float* op = O + (size_t)t * Dm;
#pragma unroll
    for (int i = 0; i < 4; i++) {
        int d = tid + i * 256;
        op[d] = (v[i] - mean) * rstd * gw[d] + bw[d];
    }
}

// ---------------- fused MoE combine + layernorm (replaces zero/scatter/ln) ----------------
__global__ void k_moe_out(const float* __restrict__ X2,
                          const float* __restrict__ gw, const float* __restrict__ bw,
                          float* __restrict__ O)
{
    int t = blockIdx.x, tid = threadIdx.x;
    int p0 = g_tok_pos[t * 2], p1 = g_tok_pos[t * 2 + 1];
    float w0 = g_tok_g[t * 2], w1 = g_tok_g[t * 2 + 1];
    const float* xp = X2 + (size_t)t * Dm;
    const float* y0 = g_YG + (size_t)p0 * Dm;
    const float* y1 = g_YG + (size_t)p1 * Dm;
    float v[4]; float s = 0.f;
#pragma unroll
    for (int i = 0; i < 4; i++) {
        int d = tid + i * 256;
        v[i] = xp[d] + w0 * y0[d] + w1 * y1[d];
        s += v[i];
    }
    __shared__ float red[256];
    red[tid] = s; __syncthreads();
    for (int st = 128; st > 0; st >>= 1) {
        if (tid < st) red[tid] += red[tid + st];
        __syncthreads();
    }
    float mean = red[0] * (1.f / Dm);
    __syncthreads();
    float s2 = 0.f;
#pragma unroll
    for (int i = 0; i < 4; i++) { float dd = v[i] - mean; s2 += dd * dd; }
    red[tid] = s2; __syncthreads();
    for (int st = 128; st > 0; st >>= 1) {
        if (tid < st) red[tid] += red[tid + st];
        __syncthreads();
    }
    float rstd = rsqrtf(red[0] * (1.f / Dm) + 1e-5f);
    float* op = O + (size_t)t * Dm;
#pragma unroll
    for (int i = 0; i < 4; i++) {
        int d = tid + i * 256;
        op[d] = (v[i] - mean) * rstd * gw[d] + bw[d];
    }
}

// ---------------- MoE routing / dispatch ----------------
__global__ void k_moe_init()
{
    int tid = threadIdx.x;
    if (tid < Ee) { g_cnt[tid] = 0; g_cur[tid] = 0; }
}

__global__ void k_router(const float* __restrict__ X,
                         const float* __restrict__ rw,
                         const float* __restrict__ rb,
                         int mode)
{
    int t = blockIdx.x, tid = threadIdx.x;
    const float* xp = X + (size_t)t * Dm;
    float loc[Ee];
#pragma unroll
    for (int e = 0; e < Ee; e++) loc[e] = 0.f;
    for (int d = tid; d < Dm; d += 256) {
        float xv = xp[d];
#pragma unroll
        for (int e = 0; e < Ee; e++) loc[e] += xv * rw[d * Ee + e];
    }
    __shared__ float red[256 * Ee];
#pragma unroll
    for (int e = 0; e < Ee; e++) red[tid * Ee + e] = loc[e];
    __syncthreads();
    for (int st = 128; st > 0; st >>= 1) {
        if (tid < st)
#pragma unroll
            for (int e = 0; e < Ee; e++)
                red[tid * Ee + e] += red[(tid + st) * Ee + e];
        __syncthreads();
    }
    if (tid == 0) {
        float lg[Ee], mx = -1e30f;
#pragma unroll
        for (int e = 0; e < Ee; e++) { lg[e] = red[e] + rb[e]; mx = fmaxf(mx, lg[e]); }
        float sm = 0.f;
#pragma unroll
        for (int e = 0; e < Ee; e++) { lg[e] = expf(lg[e] - mx); sm += lg[e]; }
        float inv = 1.f / sm;
#pragma unroll
        for (int e = 0; e < Ee; e++) lg[e] *= inv;
        int e0 = 0;
#pragma unroll
        for (int e = 1; e < Ee; e++) if (lg[e] > lg[e0]) e0 = e;
        int e1 = -1;
#pragma unroll
        for (int e = 0; e < Ee; e++)
            if (e != e0 && (e1 < 0 || lg[e] > lg[e1])) e1 = e;
        if (mode == 0) {
            float g0 = lg[e0], g1 = lg[e1], gs = g0 + g1;
            g_tok_e[t * 2] = e0;  g_tok_e[t * 2 + 1] = e1;
            g_tok_g[t * 2] = g0 / gs; g_tok_g[t * 2 + 1] = g1 / gs;
            atomicAdd(&g_cnt[e0], 1); atomicAdd(&g_cnt[e1], 1);
        } else {
#pragma unroll
            for (int e = 0; e < Ee; e++) g_auxp[t * Ee + e] = lg[e];
            g_auxi[t * 2] = e0; g_auxi[t * 2 + 1] = e1;
        }
    }
}

__global__ void k_offsets()
{
    if (threadIdx.x == 0) {
        int acc = 0;
        for (int e = 0; e < Ee; e++) {
            g_off[e] = acc;
            acc += ((g_cnt[e] + 127) >> 7) << 7;
        }
        g_off[Ee] = acc;
    }
}

__global__ void k_gather(const float* __restrict__ X)
{
    int t = blockIdx.x, tid = threadIdx.x;
    __shared__ int spos[TOPK];
    if (tid == 0) {
#pragma unroll
        for (int k = 0; k < TOPK; k++) {
            int e = g_tok_e[t * 2 + k];
            int p = g_off[e] + atomicAdd(&g_cur[e], 1);
            spos[k] = p;
            g_tok_pos[t * 2 + k] = p;
        }
    }
    __syncthreads();
    const float4* src = reinterpret_cast<const float4*>(X + (size_t)t * Dm);
#pragma unroll
    for (int k = 0; k < TOPK; k++) {
        float4* dst = reinterpret_cast<float4*>(g_XG + (size_t)spos[k] * Dm);
        dst[tid] = src[tid];
    }
}

__global__ void k_aux_final(float* __restrict__ out)
{
    int tid = threadIdx.x;
    float imp[Ee];
#pragma unroll
    for (int e = 0; e < Ee; e++) imp[e] = 0.f;
    for (int t = tid; t < Ntok; t += 256)
#pragma unroll
        for (int e = 0; e < Ee; e++) imp[e] += g_auxp[t * Ee + e];
    float ld[Ee];
#pragma unroll
    for (int e = 0; e < Ee; e++) ld[e] = 0.f;
    for (int i = tid; i < Ntok * TOPK; i += 256) ld[g_auxi[i]] += 1.f;

    __shared__ float red[256 * Ee];
    __shared__ float simp[Ee];
#pragma unroll
    for (int e = 0; e < Ee; e++) red[tid * Ee + e] = imp[e];
    __syncthreads();
    for (int st = 128; st > 0; st >>= 1) {
        if (tid < st)
#pragma unroll
            for (int e = 0; e < Ee; e++)
                red[tid * Ee + e] += red[(tid + st) * Ee + e];
        __syncthreads();
    }
    if (tid == 0)
#pragma unroll
        for (int e = 0; e < Ee; e++) simp[e] = red[e];
    __syncthreads();
#pragma unroll
    for (int e = 0; e < Ee; e++) red[tid * Ee + e] = ld[e];
    __syncthreads();
    for (int st = 128; st > 0; st >>= 1) {
        if (tid < st)
#pragma unroll
            for (int e = 0; e < Ee; e++)
                red[tid * Ee + e] += red[(tid + st) * Ee + e];
        __syncthreads();
    }
    if (tid == 0) {
        float aux = 0.f;
#pragma unroll
        for (int e = 0; e < Ee; e++)
            aux += (simp[e] / (float)Ntok) * (red[e] / (float)(Ntok * TOPK));
        out[0] = (float)Ee * aux;
    }
}

// ---------------- host orchestration ----------------
extern "C" void kernel_launch(void* const* d_in, const int* in_sizes, int n_in,
                              void* d_out, int out_size)
{
    (void)in_sizes; (void)n_in;
    const float* x     = (const float*)d_in[0];
    const float* enc   = (const float*)d_in[1];
    const float* sa_wq = (const float*)d_in[2];
    const float* sa_bq = (const float*)d_in[3];
    const float* sa_wk = (const float*)d_in[4];
    const float* sa_bk = (const float*)d_in[5];
    const float* sa_wv = (const float*)d_in[6];
    const float* sa_bv = (const float*)d_in[7];
    const float* sa_wo = (const float*)d_in[8];
    const float* sa_bo = (const float*)d_in[9];
    const float* ca_wq = (const float*)d_in[10];
    const float* ca_bq = (const float*)d_in[11];
    const float* ca_wk = (const float*)d_in[12];
    const float* ca_bk = (const float*)d_in[13];
    const float* ca_wv = (const float*)d_in[14];
    const float* ca_bv = (const float*)d_in[15];
    const float* ca_wo = (const float*)d_in[16];
    const float* ca_bo = (const float*)d_in[17];
    const float* n1_g  = (const float*)d_in[18];
    const float* n1_b  = (const float*)d_in[19];
    const float* n2_g  = (const float*)d_in[20];
    const float* n2_b  = (const float*)d_in[21];
    const float* n3_g  = (const float*)d_in[22];
    const float* n3_b  = (const float*)d_in[23];
    const float* r_w   = (const float*)d_in[24];
    const float* r_b   = (const float*)d_in[25];
    const float* e_w1  = (const float*)d_in[26];
    const float* e_b1  = (const float*)d_in[27];
    const float* e_w2  = (const float*)d_in[28];
    const float* e_b2  = (const float*)d_in[29];

    void *pQ, *pK, *pV, *pAT, *pPR, *pX1, *pX2, *pXG, *pHB, *pYG;
    cudaGetSymbolAddress(&pQ,  g_Q);
    cudaGetSymbolAddress(&pK,  g_K);
    cudaGetSymbolAddress(&pV,  g_V);
    cudaGetSymbolAddress(&pAT, g_AT);
    cudaGetSymbolAddress(&pPR, g_PR);
    cudaGetSymbolAddress(&pX1, g_X1);
    cudaGetSymbolAddress(&pX2, g_X2);
    cudaGetSymbolAddress(&pXG, g_XG);
    cudaGetSymbolAddress(&pHB, g_HB);
    cudaGetSymbolAddress(&pYG, g_YG);
    float* Q  = (float*)pQ;  float* K  = (float*)pK;  float* V  = (float*)pV;
    float* AT = (float*)pAT; float* PR = (float*)pPR;
    float* X1 = (float*)pX1; float* X2 = (float*)pX2;
    float* XG = (float*)pXG; float* HB = (float*)pHB; float* YG = (float*)pYG;
    float* out = (float*)d_out;

    static int smem_set = 0;
    if (!smem_set) {
        cudaFuncSetAttribute(k_flash, cudaFuncAttributeMaxDynamicSharedMemorySize, FLASH_SMEM);
        cudaFuncSetAttribute(k_gemm128, cudaFuncAttributeMaxDynamicSharedMemorySize, GEMM_SMEM);
        cudaFuncSetAttribute(k_moe_gemm_mma, cudaFuncAttributeMaxDynamicSharedMemorySize, GEMM_SMEM);
        smem_set = 1;
    }

    dim3 gblk(128);
    dim3 blk(256);
    dim3 gProj(Ntok / 128, Dm / 128);
    dim3 gFlash(Sseq / QT, Bbat * Hh);

    // ---- self attention ----
    k_gemm128<<<gProj, gblk, GEMM_SMEM>>>(x, Dm, sa_wq, Dm, sa_bq, Q, Dm, Ntok, Dm, 0);
    k_gemm128<<<gProj, gblk, GEMM_SMEM>>>(x, Dm, sa_wk, Dm, sa_bk, K, Dm, Ntok, Dm, 0);
    k_gemm128<<<gProj, gblk, GEMM_SMEM>>>(x, Dm, sa_wv, Dm, sa_bv, V, Dm, Ntok, Dm, 0);
    k_flash<<<gFlash, blk, FLASH_SMEM>>>(Q, K, V, AT);
    k_gemm128<<<gProj, gblk, GEMM_SMEM>>>(AT, Dm, sa_wo, Dm, sa_bo, PR, Dm, Ntok, Dm, 0);
    k_ln_res<<<Ntok, blk>>>(x, PR, n1_g, n1_b, X1);

    // ---- cross attention ----
    k_gemm128<<<gProj, gblk, GEMM_SMEM>>>(X1,  Dm, ca_wq, Dm, ca_bq, Q, Dm, Ntok, Dm, 0);
    k_gemm128<<<gProj, gblk, GEMM_SMEM>>>(enc, Dm, ca_wk, Dm, ca_bk, K, Dm, Ntok, Dm, 0);
    k_gemm128<<<gProj, gblk, GEMM_SMEM>>>(enc, Dm, ca_wv, Dm, ca_bv, V, Dm, Ntok, Dm, 0);
    k_flash<<<gFlash, blk, FLASH_SMEM>>>(Q, K, V, AT);
    k_gemm128<<<gProj, gblk, GEMM_SMEM>>>(AT, Dm, ca_wo, Dm, ca_bo, PR, Dm, Ntok, Dm, 0);
    k_ln_res<<<Ntok, blk>>>(X1, PR, n2_g, n2_b, X2);

    // ---- MoE (sparse top-2 dispatch) ----
    k_moe_init<<<1, blk>>>();
    k_router<<<Ntok, blk>>>(X2, r_w, r_b, 0);
    k_offsets<<<1, 1>>>();
    k_gather<<<Ntok, blk>>>(X2);
    k_moe_gemm_mma<<<dim3(Ntok / 128, Ff / 128, Ee), gblk, GEMM_SMEM>>>(XG, e_w1, e_b1, HB, Dm, Ff, 1);
    k_moe_gemm_mma<<<dim3(Ntok / 128, Dm / 128, Ee), gblk, GEMM_SMEM>>>(HB, e_w2, e_b2, YG, Ff, Dm, 0);
    k_moe_out<<<Ntok, blk>>>(X2, n3_g, n3_b, out);

    // ---- aux loss (router recompute on OUTPUT, per reference) ----
    if (out_size > Ntok * Dm) {
        k_router<<<Ntok, blk>>>(out, r_w, r_b, 1);
        k_aux_final<<<1, blk>>>(out + (out_size - 1));
    }
}